// round 4
// baseline (speedup 1.0000x reference)
#include <cuda_runtime.h>
#include <math.h>

// Problem constants
#define BB   4
#define TT   4096
#define DD   1024
#define HH   4
#define DKK  256
#define NTOK (BB * TT)          // 16384 tokens
#define NROW (NTOK * HH)        // 65536 head-rows of 256

// ---------------------------------------------------------------------------
// Scratch (device globals: no allocation allowed in kernel_launch)
// ---------------------------------------------------------------------------
__device__ float g_q[NTOK * DD];     // q projection (then normalized q)
__device__ float g_k[NTOK * DD];     // k projection (then normalized k)
__device__ float g_v[NTOK * DD];     // v projection
__device__ float g_g[NTOK * DD];     // output gate projection
__device__ float g_o[NTOK * DD];     // recurrence output, then gated-normed y
__device__ float g_beta[NTOK * HH];
__device__ float g_dec[NTOK * HH];

// ---------------------------------------------------------------------------
// fp32 SGEMM: C[M,N] = A[M,K] @ B[K,N], all row-major, exact tiles
// 128x128 block, 8x8 per thread, BK=8, double-buffered smem
// ---------------------------------------------------------------------------
#define GBM 128
#define GBN 128
#define GBK 8
#define GTM 8
#define GTN 8

__global__ void __launch_bounds__(256)
sgemm_kernel(const float* __restrict__ A, const float* __restrict__ B,
             float* __restrict__ C, int M, int N, int K)
{
    __shared__ __align__(16) float As[2][GBK][GBM];
    __shared__ __align__(16) float Bs[2][GBK][GBN];

    const int tid = threadIdx.x;
    const int tx  = tid & 15;          // 0..15  (N direction)
    const int ty  = tid >> 4;          // 0..15  (M direction)
    const int blockRow = blockIdx.y * GBM;
    const int blockCol = blockIdx.x * GBN;

    const float* Ab = A + (size_t)blockRow * K;
    const float* Bb = B + blockCol;

    const int aRow = tid >> 1;          // 0..127
    const int aCol = (tid & 1) * 4;     // 0 or 4
    const int bRow = tid >> 5;          // 0..7
    const int bCol = (tid & 31) * 4;    // 0..124

    float acc[GTM][GTN];
#pragma unroll
    for (int i = 0; i < GTM; i++)
#pragma unroll
        for (int j = 0; j < GTN; j++) acc[i][j] = 0.f;

    // load tile 0
    {
        float4 a = *(const float4*)(Ab + (size_t)aRow * K + aCol);
        As[0][aCol + 0][aRow] = a.x;
        As[0][aCol + 1][aRow] = a.y;
        As[0][aCol + 2][aRow] = a.z;
        As[0][aCol + 3][aRow] = a.w;
        float4 b = *(const float4*)(Bb + (size_t)bRow * N + bCol);
        *(float4*)&Bs[0][bRow][bCol] = b;
    }
    __syncthreads();

    const int nt = K >> 3;
    for (int t = 0; t < nt; t++) {
        const int cur = t & 1;
        const int nxt = cur ^ 1;
        float4 an = make_float4(0.f, 0.f, 0.f, 0.f);
        float4 bn = make_float4(0.f, 0.f, 0.f, 0.f);
        if (t + 1 < nt) {
            const int k0 = (t + 1) * GBK;
            an = *(const float4*)(Ab + (size_t)aRow * K + k0 + aCol);
            bn = *(const float4*)(Bb + (size_t)(k0 + bRow) * N + bCol);
        }

#pragma unroll
        for (int kk = 0; kk < GBK; kk++) {
            float ra[GTM], rb[GTN];
            float4 a0 = *(const float4*)&As[cur][kk][ty * GTM];
            float4 a1 = *(const float4*)&As[cur][kk][ty * GTM + 4];
            float4 b0 = *(const float4*)&Bs[cur][kk][tx * GTN];
            float4 b1 = *(const float4*)&Bs[cur][kk][tx * GTN + 4];
            ra[0] = a0.x; ra[1] = a0.y; ra[2] = a0.z; ra[3] = a0.w;
            ra[4] = a1.x; ra[5] = a1.y; ra[6] = a1.z; ra[7] = a1.w;
            rb[0] = b0.x; rb[1] = b0.y; rb[2] = b0.z; rb[3] = b0.w;
            rb[4] = b1.x; rb[5] = b1.y; rb[6] = b1.z; rb[7] = b1.w;
#pragma unroll
            for (int i = 0; i < GTM; i++)
#pragma unroll
                for (int j = 0; j < GTN; j++)
                    acc[i][j] = fmaf(ra[i], rb[j], acc[i][j]);
        }

        if (t + 1 < nt) {
            As[nxt][aCol + 0][aRow] = an.x;
            As[nxt][aCol + 1][aRow] = an.y;
            As[nxt][aCol + 2][aRow] = an.z;
            As[nxt][aCol + 3][aRow] = an.w;
            *(float4*)&Bs[nxt][bRow][bCol] = bn;
        }
        __syncthreads();
    }

    float* Cb = C + (size_t)(blockRow + ty * GTM) * N + blockCol + tx * GTN;
#pragma unroll
    for (int i = 0; i < GTM; i++) {
        *(float4*)(Cb + (size_t)i * N)     = make_float4(acc[i][0], acc[i][1], acc[i][2], acc[i][3]);
        *(float4*)(Cb + (size_t)i * N + 4) = make_float4(acc[i][4], acc[i][5], acc[i][6], acc[i][7]);
    }
}

// ---------------------------------------------------------------------------
// beta / dec projections: one warp per token
// beta = sigmoid(x @ Wb); dec = exp(-exp(A_log) * softplus(x @ Wa + dt_bias))
// ---------------------------------------------------------------------------
__device__ __forceinline__ float sigmoid_f(float z) { return 1.f / (1.f + expf(-z)); }
__device__ __forceinline__ float softplus_f(float z) {
    return fmaxf(z, 0.f) + log1pf(expf(-fabsf(z)));
}

__global__ void __launch_bounds__(256)
betadec_kernel(const float* __restrict__ x, const float* __restrict__ Wb,
               const float* __restrict__ Wa, const float* __restrict__ A_log,
               const float* __restrict__ dt_bias,
               float* __restrict__ Beta, float* __restrict__ Dec)
{
    const int warp = (blockIdx.x * blockDim.x + threadIdx.x) >> 5;
    const int lane = threadIdx.x & 31;
    if (warp >= NTOK) return;

    const float* xr = x + (size_t)warp * DD;
    const float4* Wb4 = (const float4*)Wb;   // [D] rows of 4
    const float4* Wa4 = (const float4*)Wa;

    float b0 = 0.f, b1 = 0.f, b2 = 0.f, b3 = 0.f;
    float a0 = 0.f, a1 = 0.f, a2 = 0.f, a3 = 0.f;
#pragma unroll 4
    for (int i = 0; i < DD / 32; i++) {
        const int d = i * 32 + lane;
        const float xv = xr[d];
        const float4 wb = Wb4[d];
        const float4 wa = Wa4[d];
        b0 = fmaf(xv, wb.x, b0); b1 = fmaf(xv, wb.y, b1);
        b2 = fmaf(xv, wb.z, b2); b3 = fmaf(xv, wb.w, b3);
        a0 = fmaf(xv, wa.x, a0); a1 = fmaf(xv, wa.y, a1);
        a2 = fmaf(xv, wa.z, a2); a3 = fmaf(xv, wa.w, a3);
    }
#pragma unroll
    for (int off = 16; off; off >>= 1) {
        b0 += __shfl_xor_sync(0xffffffffu, b0, off);
        b1 += __shfl_xor_sync(0xffffffffu, b1, off);
        b2 += __shfl_xor_sync(0xffffffffu, b2, off);
        b3 += __shfl_xor_sync(0xffffffffu, b3, off);
        a0 += __shfl_xor_sync(0xffffffffu, a0, off);
        a1 += __shfl_xor_sync(0xffffffffu, a1, off);
        a2 += __shfl_xor_sync(0xffffffffu, a2, off);
        a3 += __shfl_xor_sync(0xffffffffu, a3, off);
    }
    if (lane == 0) {
        float bl[4] = {b0, b1, b2, b3};
        float al[4] = {a0, a1, a2, a3};
#pragma unroll
        for (int h = 0; h < HH; h++) {
            Beta[warp * HH + h] = sigmoid_f(bl[h]);
            Dec[warp * HH + h]  = expf(-expf(A_log[h]) * softplus_f(al[h] + dt_bias[h]));
        }
    }
}

// ---------------------------------------------------------------------------
// q/k L2 normalization (in place): one warp per head-row of 256
// q *= rsqrt(sum q^2 + 1e-6) / 16 ; k *= rsqrt(sum k^2 + 1e-6)
// ---------------------------------------------------------------------------
__global__ void __launch_bounds__(256)
qknorm_kernel(float* __restrict__ Q, float* __restrict__ Kk)
{
    const int warp = (blockIdx.x * blockDim.x + threadIdx.x) >> 5;
    const int lane = threadIdx.x & 31;
    if (warp >= NROW) return;

    float* qr = Q + (size_t)warp * DKK;
    float* kr = Kk + (size_t)warp * DKK;

    float4 q0 = *(float4*)(qr + lane * 8);
    float4 q1 = *(float4*)(qr + lane * 8 + 4);
    float4 k0 = *(float4*)(kr + lane * 8);
    float4 k1 = *(float4*)(kr + lane * 8 + 4);

    float sq = q0.x*q0.x + q0.y*q0.y + q0.z*q0.z + q0.w*q0.w
             + q1.x*q1.x + q1.y*q1.y + q1.z*q1.z + q1.w*q1.w;
    float sk = k0.x*k0.x + k0.y*k0.y + k0.z*k0.z + k0.w*k0.w
             + k1.x*k1.x + k1.y*k1.y + k1.z*k1.z + k1.w*k1.w;
#pragma unroll
    for (int off = 16; off; off >>= 1) {
        sq += __shfl_xor_sync(0xffffffffu, sq, off);
        sk += __shfl_xor_sync(0xffffffffu, sk, off);
    }
    const float qs = rsqrtf(sq + 1e-6f) * 0.0625f;   // * DK^-0.5 (1/16)
    const float ks = rsqrtf(sk + 1e-6f);

    q0.x *= qs; q0.y *= qs; q0.z *= qs; q0.w *= qs;
    q1.x *= qs; q1.y *= qs; q1.z *= qs; q1.w *= qs;
    k0.x *= ks; k0.y *= ks; k0.z *= ks; k0.w *= ks;
    k1.x *= ks; k1.y *= ks; k1.z *= ks; k1.w *= ks;

    *(float4*)(qr + lane * 8)     = q0;
    *(float4*)(qr + lane * 8 + 4) = q1;
    *(float4*)(kr + lane * 8)     = k0;
    *(float4*)(kr + lane * 8 + 4) = k1;
}

// ---------------------------------------------------------------------------
// Gated delta-rule recurrence.
// Grid (8, H, B): each CTA owns (b, h) and 32 DV columns (group g).
// 8 warps cover DK=256 (32 rows each); lane = column within group.
// State S[dk][col] in registers: 32 per thread.
// Per step: S*=dec; pred = k^T S; S += k (beta(v - pred))^T; o = q^T S.
// ---------------------------------------------------------------------------
__global__ void __launch_bounds__(256)
recur_kernel(const float* __restrict__ Q, const float* __restrict__ Kmat,
             const float* __restrict__ V, const float* __restrict__ Beta,
             const float* __restrict__ Dec, float* __restrict__ O)
{
    const int g    = blockIdx.x;       // column group (32 cols)
    const int h    = blockIdx.y;
    const int b    = blockIdx.z;
    const int tid  = threadIdx.x;
    const int w    = tid >> 5;
    const int lane = tid & 31;

    __shared__ __align__(16) float sk[256];
    __shared__ __align__(16) float sq[256];
    __shared__ float sv[32];
    __shared__ float part[8][32];
    __shared__ float part2[8][32];
    __shared__ float sbd[2];

    float S[32];
#pragma unroll
    for (int i = 0; i < 32; i++) S[i] = 0.f;

    const size_t base = ((size_t)b * TT) * DD + (size_t)h * DKK;
    const float* qp = Q + base;
    const float* kp = Kmat + base;
    const float* vp = V + base + g * 32;
    float*       op = O + base + g * 32;
    const float* bp = Beta + ((size_t)b * TT) * HH + h;
    const float* dp = Dec  + ((size_t)b * TT) * HH + h;

    // prefetch step 0 into registers
    float kn = kp[tid];
    float qn = qp[tid];
    float vn = (w == 0) ? vp[lane] : 0.f;
    float bn = 0.f, dn = 0.f;
    if (tid == 0) { bn = *bp; dn = *dp; }

    for (int t = 0; t < TT; t++) {
        // publish step-t operands
        sk[tid] = kn;
        sq[tid] = qn;
        if (w == 0) sv[lane] = vn;
        if (tid == 0) { sbd[0] = bn; sbd[1] = dn; }
        __syncthreads();                             // A

        // prefetch step t+1 (latency hidden behind compute)
        if (t + 1 < TT) {
            kp += DD; qp += DD; vp += DD; bp += HH; dp += HH;
            kn = kp[tid];
            qn = qp[tid];
            if (w == 0) vn = vp[lane];
            if (tid == 0) { bn = *bp; dn = *dp; }
        }

        const float bt  = sbd[0];
        const float dct = sbd[1];

        // decay + pred partial for this warp's DK slice
        float kreg[32];
        float p = 0.f;
        const float4* sk4 = (const float4*)(sk + w * 32);
#pragma unroll
        for (int ii = 0; ii < 8; ii++) {
            float4 k4 = sk4[ii];
            kreg[4*ii+0] = k4.x; kreg[4*ii+1] = k4.y;
            kreg[4*ii+2] = k4.z; kreg[4*ii+3] = k4.w;
            S[4*ii+0] *= dct; p = fmaf(k4.x, S[4*ii+0], p);
            S[4*ii+1] *= dct; p = fmaf(k4.y, S[4*ii+1], p);
            S[4*ii+2] *= dct; p = fmaf(k4.z, S[4*ii+2], p);
            S[4*ii+3] *= dct; p = fmaf(k4.w, S[4*ii+3], p);
        }
        part[w][lane] = p;
        __syncthreads();                             // B

        // full pred (redundantly per warp: cheap, avoids a broadcast sync)
        float pred = 0.f;
#pragma unroll
        for (int ww = 0; ww < 8; ww++) pred += part[ww][lane];
        const float u = bt * (sv[lane] - pred);

        // rank-1 update + output partial
        float ov = 0.f;
        const float4* sq4 = (const float4*)(sq + w * 32);
#pragma unroll
        for (int ii = 0; ii < 8; ii++) {
            float4 q4 = sq4[ii];
            S[4*ii+0] = fmaf(kreg[4*ii+0], u, S[4*ii+0]); ov = fmaf(q4.x, S[4*ii+0], ov);
            S[4*ii+1] = fmaf(kreg[4*ii+1], u, S[4*ii+1]); ov = fmaf(q4.y, S[4*ii+1], ov);
            S[4*ii+2] = fmaf(kreg[4*ii+2], u, S[4*ii+2]); ov = fmaf(q4.z, S[4*ii+2], ov);
            S[4*ii+3] = fmaf(kreg[4*ii+3], u, S[4*ii+3]); ov = fmaf(q4.w, S[4*ii+3], ov);
        }
        part2[w][lane] = ov;
        __syncthreads();                             // C

        if (w == 0) {
            float o = 0.f;
#pragma unroll
            for (int ww = 0; ww < 8; ww++) o += part2[ww][lane];
            op[lane] = o;
        }
        op += DD;
    }
}

// ---------------------------------------------------------------------------
// Epilogue: gated RMSNorm per head-row of 256 (one warp per row), in place.
// y = o * rsqrt(mean(o^2)+1e-5) * norm_w * silu(gate)
// ---------------------------------------------------------------------------
__global__ void __launch_bounds__(256)
epilogue_kernel(float* __restrict__ Oarr, const float* __restrict__ G,
                const float* __restrict__ norm_w)
{
    const int warp = (blockIdx.x * blockDim.x + threadIdx.x) >> 5;
    const int lane = threadIdx.x & 31;
    if (warp >= NROW) return;

    float* orow = Oarr + (size_t)warp * DKK;
    const float* grow = G + (size_t)warp * DKK;

    float4 o0 = *(float4*)(orow + lane * 8);
    float4 o1 = *(float4*)(orow + lane * 8 + 4);

    float s = o0.x*o0.x + o0.y*o0.y + o0.z*o0.z + o0.w*o0.w
            + o1.x*o1.x + o1.y*o1.y + o1.z*o1.z + o1.w*o1.w;
#pragma unroll
    for (int off = 16; off; off >>= 1)
        s += __shfl_xor_sync(0xffffffffu, s, off);
    const float scale = rsqrtf(s * (1.f / 256.f) + 1e-5f);

    float4 g0 = *(const float4*)(grow + lane * 8);
    float4 g1 = *(const float4*)(grow + lane * 8 + 4);
    float4 w0 = *(const float4*)(norm_w + lane * 8);
    float4 w1 = *(const float4*)(norm_w + lane * 8 + 4);

    o0.x = o0.x * scale * w0.x * (g0.x * sigmoid_f(g0.x));
    o0.y = o0.y * scale * w0.y * (g0.y * sigmoid_f(g0.y));
    o0.z = o0.z * scale * w0.z * (g0.z * sigmoid_f(g0.z));
    o0.w = o0.w * scale * w0.w * (g0.w * sigmoid_f(g0.w));
    o1.x = o1.x * scale * w1.x * (g1.x * sigmoid_f(g1.x));
    o1.y = o1.y * scale * w1.y * (g1.y * sigmoid_f(g1.y));
    o1.z = o1.z * scale * w1.z * (g1.z * sigmoid_f(g1.z));
    o1.w = o1.w * scale * w1.w * (g1.w * sigmoid_f(g1.w));

    *(float4*)(orow + lane * 8)     = o0;
    *(float4*)(orow + lane * 8 + 4) = o1;
}

// ---------------------------------------------------------------------------
// Host launcher (graph-capturable: launches only)
// ---------------------------------------------------------------------------
extern "C" void kernel_launch(void* const* d_in, const int* in_sizes, int n_in,
                              void* d_out, int out_size)
{
    const float* x       = (const float*)d_in[0];
    const float* Wq      = (const float*)d_in[1];
    const float* Wk      = (const float*)d_in[2];
    const float* Wv      = (const float*)d_in[3];
    const float* Wb      = (const float*)d_in[4];
    const float* Wa      = (const float*)d_in[5];
    const float* A_log   = (const float*)d_in[6];
    const float* dt_bias = (const float*)d_in[7];
    const float* Wg      = (const float*)d_in[8];
    const float* norm_w  = (const float*)d_in[9];
    const float* Wo      = (const float*)d_in[10];
    float* out = (float*)d_out;

    float *q, *k, *v, *g, *o, *bet, *dec;
    cudaGetSymbolAddress((void**)&q,   g_q);
    cudaGetSymbolAddress((void**)&k,   g_k);
    cudaGetSymbolAddress((void**)&v,   g_v);
    cudaGetSymbolAddress((void**)&g,   g_g);
    cudaGetSymbolAddress((void**)&o,   g_o);
    cudaGetSymbolAddress((void**)&bet, g_beta);
    cudaGetSymbolAddress((void**)&dec, g_dec);

    dim3 gemmGrid(DD / GBN, NTOK / GBM);   // (8, 128)

    sgemm_kernel<<<gemmGrid, 256>>>(x, Wq, q, NTOK, DD, DD);
    sgemm_kernel<<<gemmGrid, 256>>>(x, Wk, k, NTOK, DD, DD);
    sgemm_kernel<<<gemmGrid, 256>>>(x, Wv, v, NTOK, DD, DD);
    sgemm_kernel<<<gemmGrid, 256>>>(x, Wg, g, NTOK, DD, DD);

    betadec_kernel<<<NTOK / 8, 256>>>(x, Wb, Wa, A_log, dt_bias, bet, dec);
    qknorm_kernel<<<NROW / 8, 256>>>(q, k);

    recur_kernel<<<dim3(8, HH, BB), 256>>>(q, k, v, bet, dec, o);

    epilogue_kernel<<<NROW / 8, 256>>>(o, g, norm_w);

    sgemm_kernel<<<gemmGrid, 256>>>(o, Wo, out, NTOK, DD, DD);
}

// round 6
// speedup vs baseline: 1.6281x; 1.6281x over previous
#include <cuda_runtime.h>
#include <math.h>

// Problem constants
#define BB   4
#define TT   4096
#define DD   1024
#define HH   4
#define DKK  256
#define NTOK (BB * TT)          // 16384 tokens
#define NROW (NTOK * HH)        // 65536 head-rows of 256

// ---------------------------------------------------------------------------
// Scratch (device globals)
// ---------------------------------------------------------------------------
__device__ float g_q[NTOK * DD];
__device__ float g_k[NTOK * DD];
__device__ float g_v[NTOK * DD];
__device__ float g_g[NTOK * DD];
__device__ float g_o[NTOK * DD];
__device__ float g_beta[NTOK * HH];
__device__ float g_dec[NTOK * HH];
__device__ float g_wt[5][DD * DD];   // transposed weights [N][K]

// ---------------------------------------------------------------------------
// Small PTX helpers
// ---------------------------------------------------------------------------
__device__ __forceinline__ unsigned f2tf32(float f) {
    unsigned u; asm("cvt.rna.tf32.f32 %0, %1;" : "=r"(u) : "f"(f)); return u;
}
__device__ __forceinline__ void ldsm4(unsigned* r, unsigned addr) {
    asm volatile("ldmatrix.sync.aligned.m8n8.x4.shared.b16 {%0,%1,%2,%3}, [%4];"
                 : "=r"(r[0]), "=r"(r[1]), "=r"(r[2]), "=r"(r[3]) : "r"(addr));
}
__device__ __forceinline__ void mma8(float* c, const unsigned* a, const unsigned* b) {
    asm volatile("mma.sync.aligned.m16n8k8.row.col.f32.tf32.tf32.f32 "
                 "{%0,%1,%2,%3},{%4,%5,%6,%7},{%8,%9},{%0,%1,%2,%3};"
                 : "+f"(c[0]), "+f"(c[1]), "+f"(c[2]), "+f"(c[3])
                 : "r"(a[0]), "r"(a[1]), "r"(a[2]), "r"(a[3]),
                   "r"(b[0]), "r"(b[1]));
}
typedef unsigned long long u64;
__device__ __forceinline__ u64 pk2(float lo, float hi) {
    u64 r; asm("mov.b64 %0, {%1,%2};" : "=l"(r) : "f"(lo), "f"(hi)); return r;
}
__device__ __forceinline__ float psum2(u64 v) {
    float a, b; asm("mov.b64 {%0,%1}, %2;" : "=f"(a), "=f"(b) : "l"(v)); return a + b;
}
__device__ __forceinline__ u64 fma2(u64 a, u64 b, u64 c) {
    u64 d; asm("fma.rn.f32x2 %0, %1, %2, %3;" : "=l"(d) : "l"(a), "l"(b), "l"(c)); return d;
}
__device__ __forceinline__ u64 mul2(u64 a, u64 b) {
    u64 d; asm("mul.rn.f32x2 %0, %1, %2;" : "=l"(d) : "l"(a), "l"(b)); return d;
}
__device__ __forceinline__ float sigmoid_f(float z) { return 1.f / (1.f + expf(-z)); }
__device__ __forceinline__ float softplus_f(float z) {
    return fmaxf(z, 0.f) + log1pf(expf(-fabsf(z)));
}

// ---------------------------------------------------------------------------
// 1024x1024 transpose (for weight matrices): out[n][k] = in[k][n]
// ---------------------------------------------------------------------------
__global__ void __launch_bounds__(256)
transpose_kernel(const float* __restrict__ in, float* __restrict__ out)
{
    __shared__ float tl[32][33];
    const int tx = threadIdx.x, ty = threadIdx.y;
    const int x  = blockIdx.x * 32 + tx;
    const int y0 = blockIdx.y * 32;
#pragma unroll
    for (int j = 0; j < 32; j += 8)
        tl[ty + j][tx] = in[(size_t)(y0 + ty + j) * DD + x];
    __syncthreads();
    const int ox  = blockIdx.y * 32 + tx;
    const int oy0 = blockIdx.x * 32;
#pragma unroll
    for (int j = 0; j < 32; j += 8)
        out[(size_t)(oy0 + ty + j) * DD + ox] = tl[tx][ty + j];
}

// ---------------------------------------------------------------------------
// tf32 tensor-core GEMM: C[M,N] = A[M,K] @ Bt[N,K]^T  (fp32 in/out)
// 128x128x32 CTA tile, 8 warps in 4(M)x2(N), warp tile 32x64, m16n8k8 mma.
// XOR swizzle: 16B chunk c of row r stored at chunk (c ^ (r&7)).
// ---------------------------------------------------------------------------
#define TBM 128
#define TBN 128
#define TBK 32

__global__ void __launch_bounds__(256)
gemm_tf32_kernel(const float* __restrict__ A, const float* __restrict__ Bt,
                 float* __restrict__ C, int M, int N, int K)
{
    __shared__ __align__(16) unsigned As[TBM * TBK];
    __shared__ __align__(16) unsigned Bs[TBN * TBK];

    const int tid   = threadIdx.x;
    const int warp  = tid >> 5;
    const int lane  = tid & 31;
    const int warpM = warp & 3;          // 0..3
    const int warpN = warp >> 2;         // 0..1
    const int blockRow = blockIdx.y * TBM;
    const int blockCol = blockIdx.x * TBN;

    // staging map: thread handles rows srow+32i, 16B chunk schk
    const int srow = tid >> 3;           // 0..31
    const int schk = tid & 7;            // 0..7

    const unsigned asBase = (unsigned)__cvta_generic_to_shared(As);
    const unsigned bsBase = (unsigned)__cvta_generic_to_shared(Bs);

    // ldmatrix lane addressing (A fragments)
    const int rowA  = warpM * 32 + (lane & 15);
    const int cbitA = (lane >> 4) & 1;
    const int maskA = rowA & 7;
    unsigned rbA[2];
#pragma unroll
    for (int mt = 0; mt < 2; mt++)
        rbA[mt] = asBase + ((unsigned)(rowA + mt * 16) << 7);

    // ldmatrix lane addressing (B fragments, pairs of n-tiles)
    const int rowB  = warpN * 64 + (lane & 7) + (((lane >> 4) & 1) << 3);
    const int cbitB = (lane >> 3) & 1;
    const int maskB = rowB & 7;
    unsigned rbB[4];
#pragma unroll
    for (int p = 0; p < 4; p++)
        rbB[p] = bsBase + ((unsigned)(rowB + p * 16) << 7);

    float acc[2][8][4];
#pragma unroll
    for (int mt = 0; mt < 2; mt++)
#pragma unroll
        for (int nt = 0; nt < 8; nt++)
#pragma unroll
            for (int i = 0; i < 4; i++) acc[mt][nt][i] = 0.f;

    const float* Ag = A  + (size_t)(blockRow + srow) * K + schk * 4;
    const float* Bg = Bt + (size_t)(blockCol + srow) * K + schk * 4;

    float4 ra[4], rb[4];
#pragma unroll
    for (int i = 0; i < 4; i++) {
        ra[i] = *(const float4*)(Ag + (size_t)(32 * i) * K);
        rb[i] = *(const float4*)(Bg + (size_t)(32 * i) * K);
    }
    // stage tile 0
#pragma unroll
    for (int i = 0; i < 4; i++) {
        const int row = srow + 32 * i;
        const int idx = row * 32 + ((schk ^ (row & 7)) << 2);
        *(uint4*)&As[idx] = make_uint4(f2tf32(ra[i].x), f2tf32(ra[i].y),
                                       f2tf32(ra[i].z), f2tf32(ra[i].w));
        *(uint4*)&Bs[idx] = make_uint4(f2tf32(rb[i].x), f2tf32(rb[i].y),
                                       f2tf32(rb[i].z), f2tf32(rb[i].w));
    }
    __syncthreads();

    const int nt_iters = K / TBK;
    for (int t = 0; t < nt_iters; t++) {
        if (t + 1 < nt_iters) {
            Ag += TBK; Bg += TBK;
#pragma unroll
            for (int i = 0; i < 4; i++) {
                ra[i] = *(const float4*)(Ag + (size_t)(32 * i) * K);
                rb[i] = *(const float4*)(Bg + (size_t)(32 * i) * K);
            }
        }

#pragma unroll
        for (int kk = 0; kk < 4; kk++) {
            unsigned af[2][4];
#pragma unroll
            for (int mt = 0; mt < 2; mt++) {
                const unsigned addr = rbA[mt] +
                    ((unsigned)(((2 * kk + cbitA) ^ maskA)) << 4);
                ldsm4(af[mt], addr);
            }
            unsigned bf[4][4];
#pragma unroll
            for (int p = 0; p < 4; p++) {
                const unsigned addr = rbB[p] +
                    ((unsigned)(((2 * kk + cbitB) ^ maskB)) << 4);
                ldsm4(bf[p], addr);
            }
#pragma unroll
            for (int mt = 0; mt < 2; mt++)
#pragma unroll
                for (int p = 0; p < 4; p++) {
                    mma8(acc[mt][2 * p],     af[mt], &bf[p][0]);
                    mma8(acc[mt][2 * p + 1], af[mt], &bf[p][2]);
                }
        }
        __syncthreads();

        if (t + 1 < nt_iters) {
#pragma unroll
            for (int i = 0; i < 4; i++) {
                const int row = srow + 32 * i;
                const int idx = row * 32 + ((schk ^ (row & 7)) << 2);
                *(uint4*)&As[idx] = make_uint4(f2tf32(ra[i].x), f2tf32(ra[i].y),
                                               f2tf32(ra[i].z), f2tf32(ra[i].w));
                *(uint4*)&Bs[idx] = make_uint4(f2tf32(rb[i].x), f2tf32(rb[i].y),
                                               f2tf32(rb[i].z), f2tf32(rb[i].w));
            }
            __syncthreads();
        }
    }

    // epilogue
#pragma unroll
    for (int mt = 0; mt < 2; mt++) {
        const int row = blockRow + warpM * 32 + mt * 16 + (lane >> 2);
#pragma unroll
        for (int nt = 0; nt < 8; nt++) {
            const int col = blockCol + warpN * 64 + nt * 8 + (lane & 3) * 2;
            *(float2*)&C[(size_t)row * N + col] =
                make_float2(acc[mt][nt][0], acc[mt][nt][1]);
            *(float2*)&C[(size_t)(row + 8) * N + col] =
                make_float2(acc[mt][nt][2], acc[mt][nt][3]);
        }
    }
}

// ---------------------------------------------------------------------------
// beta / dec projections: one warp per token
// ---------------------------------------------------------------------------
__global__ void __launch_bounds__(256)
betadec_kernel(const float* __restrict__ x, const float* __restrict__ Wb,
               const float* __restrict__ Wa, const float* __restrict__ A_log,
               const float* __restrict__ dt_bias,
               float* __restrict__ Beta, float* __restrict__ Dec)
{
    const int warp = (blockIdx.x * blockDim.x + threadIdx.x) >> 5;
    const int lane = threadIdx.x & 31;
    if (warp >= NTOK) return;

    const float* xr = x + (size_t)warp * DD;
    const float4* Wb4 = (const float4*)Wb;
    const float4* Wa4 = (const float4*)Wa;

    float b0 = 0.f, b1 = 0.f, b2 = 0.f, b3 = 0.f;
    float a0 = 0.f, a1 = 0.f, a2 = 0.f, a3 = 0.f;
#pragma unroll 4
    for (int i = 0; i < DD / 32; i++) {
        const int d = i * 32 + lane;
        const float xv = xr[d];
        const float4 wb = Wb4[d];
        const float4 wa = Wa4[d];
        b0 = fmaf(xv, wb.x, b0); b1 = fmaf(xv, wb.y, b1);
        b2 = fmaf(xv, wb.z, b2); b3 = fmaf(xv, wb.w, b3);
        a0 = fmaf(xv, wa.x, a0); a1 = fmaf(xv, wa.y, a1);
        a2 = fmaf(xv, wa.z, a2); a3 = fmaf(xv, wa.w, a3);
    }
#pragma unroll
    for (int off = 16; off; off >>= 1) {
        b0 += __shfl_xor_sync(0xffffffffu, b0, off);
        b1 += __shfl_xor_sync(0xffffffffu, b1, off);
        b2 += __shfl_xor_sync(0xffffffffu, b2, off);
        b3 += __shfl_xor_sync(0xffffffffu, b3, off);
        a0 += __shfl_xor_sync(0xffffffffu, a0, off);
        a1 += __shfl_xor_sync(0xffffffffu, a1, off);
        a2 += __shfl_xor_sync(0xffffffffu, a2, off);
        a3 += __shfl_xor_sync(0xffffffffu, a3, off);
    }
    if (lane == 0) {
        float bl[4] = {b0, b1, b2, b3};
        float al[4] = {a0, a1, a2, a3};
#pragma unroll
        for (int h = 0; h < HH; h++) {
            Beta[warp * HH + h] = sigmoid_f(bl[h]);
            Dec[warp * HH + h]  = expf(-expf(A_log[h]) * softplus_f(al[h] + dt_bias[h]));
        }
    }
}

// ---------------------------------------------------------------------------
// q/k L2 normalization
// ---------------------------------------------------------------------------
__global__ void __launch_bounds__(256)
qknorm_kernel(float* __restrict__ Q, float* __restrict__ Kk)
{
    const int warp = (blockIdx.x * blockDim.x + threadIdx.x) >> 5;
    const int lane = threadIdx.x & 31;
    if (warp >= NROW) return;

    float* qr = Q + (size_t)warp * DKK;
    float* kr = Kk + (size_t)warp * DKK;

    float4 q0 = *(float4*)(qr + lane * 8);
    float4 q1 = *(float4*)(qr + lane * 8 + 4);
    float4 k0 = *(float4*)(kr + lane * 8);
    float4 k1 = *(float4*)(kr + lane * 8 + 4);

    float sq = q0.x*q0.x + q0.y*q0.y + q0.z*q0.z + q0.w*q0.w
             + q1.x*q1.x + q1.y*q1.y + q1.z*q1.z + q1.w*q1.w;
    float sk = k0.x*k0.x + k0.y*k0.y + k0.z*k0.z + k0.w*k0.w
             + k1.x*k1.x + k1.y*k1.y + k1.z*k1.z + k1.w*k1.w;
#pragma unroll
    for (int off = 16; off; off >>= 1) {
        sq += __shfl_xor_sync(0xffffffffu, sq, off);
        sk += __shfl_xor_sync(0xffffffffu, sk, off);
    }
    const float qs = rsqrtf(sq + 1e-6f) * 0.0625f;
    const float ks = rsqrtf(sk + 1e-6f);

    q0.x *= qs; q0.y *= qs; q0.z *= qs; q0.w *= qs;
    q1.x *= qs; q1.y *= qs; q1.z *= qs; q1.w *= qs;
    k0.x *= ks; k0.y *= ks; k0.z *= ks; k0.w *= ks;
    k1.x *= ks; k1.y *= ks; k1.z *= ks; k1.w *= ks;

    *(float4*)(qr + lane * 8)     = q0;
    *(float4*)(qr + lane * 8 + 4) = q1;
    *(float4*)(kr + lane * 8)     = k0;
    *(float4*)(kr + lane * 8 + 4) = k1;
}

// ---------------------------------------------------------------------------
// Gated delta-rule recurrence — packed f32x2 math, 2 block barriers/step.
// Grid (8, H, B): CTA owns (b, h) and 32 DV columns. 8 warps cover DK=256;
// lane = column. State S (32 rows) lives in 16 packed f32x2 registers.
// Math per step (algebraically equal to reference):
//   p = k·S_old; pred = dec*p; u = beta*(v - pred);
//   S = dec*S_old + k*u;  o = q·S
// ---------------------------------------------------------------------------
__global__ void __launch_bounds__(256)
recur_kernel(const float* __restrict__ Q, const float* __restrict__ Kmat,
             const float* __restrict__ V, const float* __restrict__ Beta,
             const float* __restrict__ Dec, float* __restrict__ O)
{
    const int g    = blockIdx.x;
    const int h    = blockIdx.y;
    const int b    = blockIdx.z;
    const int tid  = threadIdx.x;
    const int w    = tid >> 5;
    const int lane = tid & 31;

    __shared__ __align__(16) float skq[512];     // k[256] | q[256]
    __shared__ float part[8][32];
    __shared__ float part2[8][32];

    u64 S2[16];
#pragma unroll
    for (int i = 0; i < 16; i++) S2[i] = 0ull;

    const size_t base = ((size_t)b * TT) * DD + (size_t)h * DKK;
    const float* qp = Q    + base + tid;
    const float* kp = Kmat + base + tid;
    const float* vp = V    + base + g * 32 + lane;
    float*       op = O    + base + g * 32;
    const float* bp = Beta + ((size_t)b * TT) * HH + h;
    const float* dp = Dec  + ((size_t)b * TT) * HH + h;

    // prefetch step 0 (every thread loads v/beta/dec — broadcast-cached)
    float kn = *kp, qn = *qp, vn = *vp, bn = *bp, dn = *dp;

#pragma unroll 1
    for (int t = 0; t < TT; t++) {
        skq[tid]       = kn;
        skq[256 + tid] = qn;
        const float vt = vn, bt = bn, dt = dn;
        __syncwarp();

        // warp-local slices, packed
        u64 k2[16], q2[16];
        {
            const ulonglong2* kk2 = (const ulonglong2*)(skq + w * 32);
            const ulonglong2* qq2 = (const ulonglong2*)(skq + 256 + w * 32);
#pragma unroll
            for (int ii = 0; ii < 8; ii++) {
                ulonglong2 kv = kk2[ii]; k2[2 * ii] = kv.x; k2[2 * ii + 1] = kv.y;
                ulonglong2 qv = qq2[ii]; q2[2 * ii] = qv.x; q2[2 * ii + 1] = qv.y;
            }
        }

        // prefetch t+1
        if (t + 1 < TT) {
            kp += DD; qp += DD; vp += DD; bp += HH; dp += HH;
            kn = *kp; qn = *qp; vn = *vp; bn = *bp; dn = *dp;
        }

        // pred partial on pre-decay state
        u64 pp = 0ull;
#pragma unroll
        for (int i = 0; i < 16; i++) pp = fma2(k2[i], S2[i], pp);
        part[w][lane] = psum2(pp);
        __syncthreads();                                   // bar 1

        float pred = 0.f;
#pragma unroll
        for (int ww = 0; ww < 8; ww++) pred += part[ww][lane];
        const float u = bt * (vt - dt * pred);
        const u64 uu = pk2(u, u);
        const u64 dd = pk2(dt, dt);

        u64 ov = 0ull;
#pragma unroll
        for (int i = 0; i < 16; i++) {
            S2[i] = fma2(dd, S2[i], mul2(k2[i], uu));
            ov    = fma2(q2[i], S2[i], ov);
        }
        part2[w][lane] = psum2(ov);
        __syncthreads();                                   // bar 2

        if (w == 0) {
            float o = 0.f;
#pragma unroll
            for (int ww = 0; ww < 8; ww++) o += part2[ww][lane];
            op[lane] = o;
        }
        op += DD;
    }
}

// ---------------------------------------------------------------------------
// Epilogue: gated RMSNorm per head-row, in place.
// ---------------------------------------------------------------------------
__global__ void __launch_bounds__(256)
epilogue_kernel(float* __restrict__ Oarr, const float* __restrict__ G,
                const float* __restrict__ norm_w)
{
    const int warp = (blockIdx.x * blockDim.x + threadIdx.x) >> 5;
    const int lane = threadIdx.x & 31;
    if (warp >= NROW) return;

    float* orow = Oarr + (size_t)warp * DKK;
    const float* grow = G + (size_t)warp * DKK;

    float4 o0 = *(float4*)(orow + lane * 8);
    float4 o1 = *(float4*)(orow + lane * 8 + 4);

    float s = o0.x*o0.x + o0.y*o0.y + o0.z*o0.z + o0.w*o0.w
            + o1.x*o1.x + o1.y*o1.y + o1.z*o1.z + o1.w*o1.w;
#pragma unroll
    for (int off = 16; off; off >>= 1)
        s += __shfl_xor_sync(0xffffffffu, s, off);
    const float scale = rsqrtf(s * (1.f / 256.f) + 1e-5f);

    float4 g0 = *(const float4*)(grow + lane * 8);
    float4 g1 = *(const float4*)(grow + lane * 8 + 4);
    float4 w0 = *(const float4*)(norm_w + lane * 8);
    float4 w1 = *(const float4*)(norm_w + lane * 8 + 4);

    o0.x = o0.x * scale * w0.x * (g0.x * sigmoid_f(g0.x));
    o0.y = o0.y * scale * w0.y * (g0.y * sigmoid_f(g0.y));
    o0.z = o0.z * scale * w0.z * (g0.z * sigmoid_f(g0.z));
    o0.w = o0.w * scale * w0.w * (g0.w * sigmoid_f(g0.w));
    o1.x = o1.x * scale * w1.x * (g1.x * sigmoid_f(g1.x));
    o1.y = o1.y * scale * w1.y * (g1.y * sigmoid_f(g1.y));
    o1.z = o1.z * scale * w1.z * (g1.z * sigmoid_f(g1.z));
    o1.w = o1.w * scale * w1.w * (g1.w * sigmoid_f(g1.w));

    *(float4*)(orow + lane * 8)     = o0;
    *(float4*)(orow + lane * 8 + 4) = o1;
}

// ---------------------------------------------------------------------------
// Host launcher
// ---------------------------------------------------------------------------
extern "C" void kernel_launch(void* const* d_in, const int* in_sizes, int n_in,
                              void* d_out, int out_size)
{
    const float* x       = (const float*)d_in[0];
    const float* Wq      = (const float*)d_in[1];
    const float* Wk      = (const float*)d_in[2];
    const float* Wv      = (const float*)d_in[3];
    const float* Wb      = (const float*)d_in[4];
    const float* Wa      = (const float*)d_in[5];
    const float* A_log   = (const float*)d_in[6];
    const float* dt_bias = (const float*)d_in[7];
    const float* Wg      = (const float*)d_in[8];
    const float* norm_w  = (const float*)d_in[9];
    const float* Wo      = (const float*)d_in[10];
    float* out = (float*)d_out;

    float *q, *k, *v, *g, *o, *bet, *dec, *wt;
    cudaGetSymbolAddress((void**)&q,   g_q);
    cudaGetSymbolAddress((void**)&k,   g_k);
    cudaGetSymbolAddress((void**)&v,   g_v);
    cudaGetSymbolAddress((void**)&g,   g_g);
    cudaGetSymbolAddress((void**)&o,   g_o);
    cudaGetSymbolAddress((void**)&bet, g_beta);
    cudaGetSymbolAddress((void**)&dec, g_dec);
    cudaGetSymbolAddress((void**)&wt,  g_wt);

    float* wtq = wt + 0 * (size_t)DD * DD;
    float* wtk = wt + 1 * (size_t)DD * DD;
    float* wtv = wt + 2 * (size_t)DD * DD;
    float* wtg = wt + 3 * (size_t)DD * DD;
    float* wto = wt + 4 * (size_t)DD * DD;

    dim3 tgrid(32, 32), tblk(32, 8);
    transpose_kernel<<<tgrid, tblk>>>(Wq, wtq);
    transpose_kernel<<<tgrid, tblk>>>(Wk, wtk);
    transpose_kernel<<<tgrid, tblk>>>(Wv, wtv);
    transpose_kernel<<<tgrid, tblk>>>(Wg, wtg);
    transpose_kernel<<<tgrid, tblk>>>(Wo, wto);

    dim3 gemmGrid(DD / TBN, NTOK / TBM);   // (8, 128)
    gemm_tf32_kernel<<<gemmGrid, 256>>>(x, wtq, q, NTOK, DD, DD);
    gemm_tf32_kernel<<<gemmGrid, 256>>>(x, wtk, k, NTOK, DD, DD);
    gemm_tf32_kernel<<<gemmGrid, 256>>>(x, wtv, v, NTOK, DD, DD);
    gemm_tf32_kernel<<<gemmGrid, 256>>>(x, wtg, g, NTOK, DD, DD);

    betadec_kernel<<<NTOK / 8, 256>>>(x, Wb, Wa, A_log, dt_bias, bet, dec);
    qknorm_kernel<<<NROW / 8, 256>>>(q, k);

    recur_kernel<<<dim3(8, HH, BB), 256>>>(q, k, v, bet, dec, o);

    epilogue_kernel<<<NROW / 8, 256>>>(o, g, norm_w);

    gemm_tf32_kernel<<<gemmGrid, 256>>>(o, wto, out, NTOK, DD, DD);
}